// round 12
// baseline (speedup 1.0000x reference)
#include <cuda_runtime.h>
#include <cuda_bf16.h>
#include <math.h>
#include <stdint.h>

#define BATCH    32768
#define DIM      256
#define MAX_IT   40
#define NCTAS    1024              // grid (4, 256)
#define EW_GRID  (BATCH*DIM/4/256)
#define YF_ELEMS (2048*16*2*32)    // [mtile][kk16][half][lane] uint4
#define XS_ELEMS (BATCH*128)       // [row*128 + col/2] uint2
#define WS_BYTES 65536             // 4096 uint4: [kk][n8l][lane]

// ---------------- device scratch ----------------
__device__ uint4 g_yf[2][YF_ELEMS];     // y as A-fragments (hi,hi,lo,lo), ping-pong
__device__ uint2 g_xs[XS_ELEMS];        // x as interleaved bf16 splits (in-place)
__device__ uint4 g_wf[16*32*32];        // W as B-fragments [kk][n8][lane]
__device__ float g_b[BATCH*DIM];
__device__ float g_WU[DIM*DIM];         // U^T for bias GEMM
__device__ __nv_bfloat16 g_w0[DIM*DIM]; // Weff hi split [k][n] (prep staging)
__device__ __nv_bfloat16 g_w1[DIM*DIM]; // Weff lo split
__device__ float g_partial[NCTAS*2];
__device__ int   g_ctr[MAX_IT+2];
__device__ int   g_active;
__device__ int   g_zpar;                // buffer index of final z (= y at exit)

// ---------------- helpers ----------------
__device__ __forceinline__ uint32_t bpack(__nv_bfloat16 a, __nv_bfloat16 b) {
    uint16_t ua = *(uint16_t*)&a, ub = *(uint16_t*)&b;
    return (uint32_t)ua | ((uint32_t)ub << 16);
}
__device__ __forceinline__ float2 bunpack(uint32_t u) {
    __nv_bfloat162 h = *(__nv_bfloat162*)&u;
    return make_float2(__bfloat162float(h.x), __bfloat162float(h.y));
}
__device__ __forceinline__ uint32_t split_hi(float a, float b,
                                             float& ra, float& rb) {
    __nv_bfloat16 ha = __float2bfloat16(a), hb = __float2bfloat16(b);
    ra = a - __bfloat162float(ha);
    rb = b - __bfloat162float(hb);
    return bpack(ha, hb);
}
__device__ __forceinline__ uint32_t pack_lo(float ra, float rb) {
    return bpack(__float2bfloat16(ra), __float2bfloat16(rb));
}
__device__ __forceinline__ void mma_bf16(float* c, const uint32_t* a, const uint32_t* b) {
    asm volatile(
        "mma.sync.aligned.m16n8k16.row.col.f32.bf16.bf16.f32 "
        "{%0,%1,%2,%3}, {%4,%5,%6,%7}, {%8,%9}, {%0,%1,%2,%3};"
        : "+f"(c[0]), "+f"(c[1]), "+f"(c[2]), "+f"(c[3])
        : "r"(a[0]), "r"(a[1]), "r"(a[2]), "r"(a[3]), "r"(b[0]), "r"(b[1]));
}

// fp32x2 helpers for the bias GEMM
__device__ __forceinline__ unsigned long long pack2(float v) {
    unsigned long long r; unsigned u = __float_as_uint(v);
    asm("mov.b64 %0, {%1, %1};" : "=l"(r) : "r"(u));
    return r;
}
__device__ __forceinline__ void ffma2(unsigned long long& d,
                                      unsigned long long a, unsigned long long b) {
    asm("fma.rn.f32x2 %0, %1, %2, %0;" : "+l"(d) : "l"(a), "l"(b));
}
__device__ __forceinline__ float lo32(unsigned long long v) {
    return __uint_as_float((unsigned)(v & 0xffffffffull));
}
__device__ __forceinline__ float hi32(unsigned long long v) {
    return __uint_as_float((unsigned)(v >> 32));
}

// ---------------- prep: U^T, Weff -> bf16 splits (row-major staging) ----------
__global__ void prep_kernel(const float* __restrict__ U,
                            const float* __restrict__ A,
                            const float* __restrict__ B) {
    int i = blockIdx.x;    // k
    int j = threadIdx.x;   // n
    g_WU[i*DIM + j] = U[j*DIM + i];
    float s = 0.f;
#pragma unroll 8
    for (int p = 0; p < DIM; ++p)
        s = fmaf(A[p*DIM + i], A[p*DIM + j], s);
    float w = -s + B[j*DIM + i] - B[i*DIM + j];
    if (i == j) w += 0.8f;                    // (1-m), m=0.2
    __nv_bfloat16 h0 = __float2bfloat16(w);
    __nv_bfloat16 h1 = __float2bfloat16(w - __bfloat162float(h0));
    g_w0[i*DIM + j] = h0;
    g_w1[i*DIM + j] = h1;
}

// ---------------- prep2: pack W into B-fragment order ----------------
// B frag m16n8k16 (col): lane T: b0={B[k0][n],B[k0+1][n]}, b1={B[k0+8][n],B[k0+9][n]}
// with k0 = kk*16 + 2*(T%4), n = n8*8 + T/4.
__global__ void prep2_kernel() {
    int kk = blockIdx.x, n8 = blockIdx.y, lane = threadIdx.x;
    int k0 = kk*16 + 2*(lane & 3);
    int n  = n8*8 + (lane >> 2);
    uint4 u;
    u.x = bpack(g_w0[(k0    )*DIM + n], g_w0[(k0+1)*DIM + n]);
    u.y = bpack(g_w0[(k0 + 8)*DIM + n], g_w0[(k0+9)*DIM + n]);
    u.z = bpack(g_w1[(k0    )*DIM + n], g_w1[(k0+1)*DIM + n]);
    u.w = bpack(g_w1[(k0 + 8)*DIM + n], g_w1[(k0+9)*DIM + n]);
    g_wf[(kk*32 + n8)*32 + lane] = u;
}

// ---------------- init: zero y frags, x splits, counters ----------------
__global__ void init_kernel() {
    int i = blockIdx.x * blockDim.x + threadIdx.x;   // 0..2M-1
    g_yf[0][i] = make_uint4(0u, 0u, 0u, 0u);
    g_xs[2*i    ] = make_uint2(0u, 0u);
    g_xs[2*i + 1] = make_uint2(0u, 0u);
    if (i == 0) { g_active = 1; g_zpar = 0; }
    if (i <= MAX_IT + 1) g_ctr[i] = 0;
}

// ---------------- bias GEMM (runs once, exact fp32): b = x @ U^T + ub ----------
__launch_bounds__(256, 2)
__global__ void bias_gemm(const float* __restrict__ Ap, const float* __restrict__ ub) {
    __shared__ float As[16][132];
    __shared__ float Bs[16][128];
    const int tid = threadIdx.x;
    const int tx  = tid & 15, ty = tid >> 4;
    const int m0  = blockIdx.y * 128, n0 = blockIdx.x * 128;
    const int ra = tid >> 2, ca = (tid & 3) << 2;
    const int rb = tid >> 5, cb = (tid & 31) << 2;
    unsigned long long acc[8][4];
#pragma unroll
    for (int i = 0; i < 8; ++i)
#pragma unroll
        for (int j = 0; j < 4; ++j) acc[i][j] = 0ull;
    for (int k0 = 0; k0 < DIM; k0 += 16) {
        float4 a0 = *(const float4*)(Ap + (m0 + ra     ) * DIM + k0 + ca);
        float4 a1 = *(const float4*)(Ap + (m0 + ra + 64) * DIM + k0 + ca);
        float4 b0 = *(const float4*)(g_WU + (k0 + rb    ) * DIM + n0 + cb);
        float4 b1 = *(const float4*)(g_WU + (k0 + rb + 8) * DIM + n0 + cb);
        __syncthreads();
        As[ca+0][ra] = a0.x;  As[ca+1][ra] = a0.y;
        As[ca+2][ra] = a0.z;  As[ca+3][ra] = a0.w;
        As[ca+0][ra+64] = a1.x;  As[ca+1][ra+64] = a1.y;
        As[ca+2][ra+64] = a1.z;  As[ca+3][ra+64] = a1.w;
        *(float4*)&Bs[rb  ][cb] = b0;
        *(float4*)&Bs[rb+8][cb] = b1;
        __syncthreads();
#pragma unroll
        for (int kk = 0; kk < 16; ++kk) {
            unsigned long long pb[4], pa[8];
#pragma unroll
            for (int j = 0; j < 4; ++j)
                pb[j] = *(const unsigned long long*)&Bs[kk][tx*2 + j*32];
#pragma unroll
            for (int i = 0; i < 8; ++i) pa[i] = pack2(As[kk][ty*8 + i]);
#pragma unroll
            for (int i = 0; i < 8; ++i)
#pragma unroll
                for (int j = 0; j < 4; ++j) ffma2(acc[i][j], pa[i], pb[j]);
        }
    }
    float2 u[4];
#pragma unroll
    for (int j = 0; j < 4; ++j) u[j] = *(const float2*)(ub + n0 + tx*2 + j*32);
#pragma unroll
    for (int i = 0; i < 8; ++i) {
        float* base = g_b + (m0 + ty*8 + i)*DIM + n0;
#pragma unroll
        for (int j = 0; j < 4; ++j) {
            float2 g;
            g.x = lo32(acc[i][j]) + u[j].x;
            g.y = hi32(acc[i][j]) + u[j].y;
            *(float2*)(base + tx*2 + j*32) = g;
        }
    }
}

// ---------------- iteration kernel (no output stores, x in-place) ----------
// CTA tile 128M x 64N; 8 warps (4 M x 2 N), warp tile 32x32.
// G = a0@w0 + a1@w0 + a0@w1; epilogue: err partials (fn in regs only),
// x' = relu(0.5*(y+G+b)) in-place; y' = x' + beta*(x'-x); merged last-CTA check.
__global__ void __launch_bounds__(256, 3)
iter_kernel(float beta, int par, int it) {
    if (g_active == 0) return;
    extern __shared__ __align__(16) uint4 ws[];   // [kk][n8l][lane] = 4096 uint4
    const int tid  = threadIdx.x;
    const int lane = tid & 31;
    const int wid  = tid >> 5;
    const int wm   = wid & 3;          // M slice (32 rows)
    const int wn   = wid >> 2;         // N slice (32 cols)
    const int mb   = blockIdx.y;       // 0..255
    const int nb   = blockIdx.x;       // 0..3

    // ---- stage this CTA's W-fragment slice (64 cols) into smem ----
#pragma unroll
    for (int j = 0; j < 16; ++j) {
        int linear = j*256 + tid;              // (kk*8 + n8l)*32 + lane
        int l  = linear & 31;
        int r  = linear >> 5;                  // 0..127
        int kk = r >> 3, n8l = r & 7;
        ws[linear] = g_wf[kk*1024 + (nb*8 + n8l)*32 + l];
    }
    __syncthreads();

    const uint4* __restrict__ yf = g_yf[par];

    float acc[2][4][4];
#pragma unroll
    for (int mi = 0; mi < 2; ++mi)
#pragma unroll
        for (int ni = 0; ni < 4; ++ni)
#pragma unroll
            for (int q = 0; q < 4; ++q) acc[mi][ni][q] = 0.f;

    const int mt0 = mb*8 + wm*2;

#pragma unroll
    for (int kk = 0; kk < 16; ++kk) {
        uint32_t ah[2][4], al[2][4];
#pragma unroll
        for (int mi = 0; mi < 2; ++mi) {
            int base = (((mt0 + mi)*16 + kk)*2)*32 + lane;
            uint4 u0 = yf[base];
            uint4 u1 = yf[base + 32];
            ah[mi][0] = u0.x; ah[mi][1] = u0.y; ah[mi][2] = u1.x; ah[mi][3] = u1.y;
            al[mi][0] = u0.z; al[mi][1] = u0.w; al[mi][2] = u1.z; al[mi][3] = u1.w;
        }
#pragma unroll
        for (int ni = 0; ni < 4; ++ni) {
            uint4 u = ws[(kk*8 + wn*4 + ni)*32 + lane];
            uint32_t bh[2] = {u.x, u.y};
            uint32_t bl[2] = {u.z, u.w};
#pragma unroll
            for (int mi = 0; mi < 2; ++mi) {
                float* c = acc[mi][ni];
                mma_bf16(c, ah[mi], bh);
                mma_bf16(c, al[mi], bh);
                mma_bf16(c, ah[mi], bl);
            }
        }
    }

    // ---- fused epilogue (x updated in place by owning thread) ----
    uint4* __restrict__ yfw = g_yf[par ^ 1];
    const int t2 = lane & 3, g = lane >> 2;
    float sn = 0.f, sd = 0.f;

#pragma unroll
    for (int mi = 0; mi < 2; ++mi) {
        int row0 = mb*128 + wm*32 + mi*16 + g;
#pragma unroll
        for (int ni = 0; ni < 4; ++ni) {
            int k8  = nb*8 + wn*4 + ni;
            int col = k8*8 + t2*2;
            int yidx = (((mt0 + mi)*16 + (k8 >> 1))*2 + (k8 & 1))*32 + lane;
            uint4 yu = yf[yidx];
            float2 a0h = bunpack(yu.x), a1h = bunpack(yu.y);
            float2 a0l = bunpack(yu.z), a1l = bunpack(yu.w);
            float y00 = a0h.x + a0l.x, y01 = a0h.y + a0l.y;
            float y10 = a1h.x + a1l.x, y11 = a1h.y + a1l.y;
            float g00 = acc[mi][ni][0], g01 = acc[mi][ni][1];
            float g10 = acc[mi][ni][2], g11 = acc[mi][ni][3];
            int gi0 = row0*DIM + col, gi1 = gi0 + 8*DIM;
            float2 b0 = *(const float2*)(g_b + gi0);
            float2 b1 = *(const float2*)(g_b + gi1);
            float fn00 = fmaxf(g00 + b0.x, 0.f), fn01 = fmaxf(g01 + b0.y, 0.f);
            float fn10 = fmaxf(g10 + b1.x, 0.f), fn11 = fmaxf(g11 + b1.y, 0.f);
            float d0 = y00-fn00, d1 = y01-fn01, d2 = y10-fn10, d3 = y11-fn11;
            sn = fmaf(d0,d0,sn); sn = fmaf(d1,d1,sn);
            sn = fmaf(d2,d2,sn); sn = fmaf(d3,d3,sn);
            sd = fmaf(y00,y00,sd); sd = fmaf(y01,y01,sd);
            sd = fmaf(y10,y10,sd); sd = fmaf(y11,y11,sd);
            float xn00 = fmaxf(0.5f*(y00 + g00 + b0.x), 0.f);
            float xn01 = fmaxf(0.5f*(y01 + g01 + b0.y), 0.f);
            float xn10 = fmaxf(0.5f*(y10 + g10 + b1.x), 0.f);
            float xn11 = fmaxf(0.5f*(y11 + g11 + b1.y), 0.f);
            int xi0 = gi0 >> 1, xi1 = gi1 >> 1;
            uint2 xu0 = g_xs[xi0], xu1 = g_xs[xi1];
            float2 x0h = bunpack(xu0.x), x0l = bunpack(xu0.y);
            float2 x1h = bunpack(xu1.x), x1l = bunpack(xu1.y);
            float yn00 = xn00 + beta*(xn00 - (x0h.x + x0l.x));
            float yn01 = xn01 + beta*(xn01 - (x0h.y + x0l.y));
            float yn10 = xn10 + beta*(xn10 - (x1h.x + x1l.x));
            float yn11 = xn11 + beta*(xn11 - (x1h.y + x1l.y));
            float r0, r1, r2, r3;
            uint32_t xh0 = split_hi(xn00, xn01, r0, r1);
            g_xs[xi0] = make_uint2(xh0, pack_lo(r0, r1));
            uint32_t xh1 = split_hi(xn10, xn11, r2, r3);
            g_xs[xi1] = make_uint2(xh1, pack_lo(r2, r3));
            uint32_t yh0 = split_hi(yn00, yn01, r0, r1);
            uint32_t yh1 = split_hi(yn10, yn11, r2, r3);
            yfw[yidx] = make_uint4(yh0, yh1, pack_lo(r0, r1), pack_lo(r2, r3));
        }
    }

    // ---- deterministic block reduction (reuse smem after sync) ----
    __syncthreads();
    float* red = (float*)ws;
    red[tid] = sn;  red[256 + tid] = sd;
    __syncthreads();
#pragma unroll
    for (int s = 128; s > 0; s >>= 1) {
        if (tid < s) { red[tid] += red[tid + s]; red[256 + tid] += red[256 + tid + s]; }
        __syncthreads();
    }
    const int cta = mb*4 + nb;
    if (tid == 0) {
        g_partial[cta*2    ] = red[0];
        g_partial[cta*2 + 1] = red[256];
    }

    // ---- merged convergence check: last CTA reduces and gates ----
    __shared__ int islast;
    __threadfence();
    if (tid == 0) islast = (atomicAdd(&g_ctr[it], 1) == NCTAS - 1);
    __syncthreads();
    if (islast) {
        float a = 0.f, b = 0.f;
#pragma unroll
        for (int k = 0; k < 4; ++k) {
            a += g_partial[2*(tid + k*256)    ];
            b += g_partial[2*(tid + k*256) + 1];
        }
        red[tid] = a; red[256 + tid] = b;
        __syncthreads();
#pragma unroll
        for (int s = 128; s > 0; s >>= 1) {
            if (tid < s) { red[tid] += red[tid + s]; red[256 + tid] += red[256 + tid + s]; }
            __syncthreads();
        }
        if (tid == 0) {
            float err = sqrtf(red[0]) / (1e-6f + sqrtf(red[256]));
            if (!(err > 1e-4f)) {
                g_active = 0;
                g_zpar = par;      // z = y of body (it) lives in buffer `par`
            }
        }
    }
}

// ---------------- final kernel: out = relu(z @ W + b), z = g_yf[g_zpar] ------
__global__ void __launch_bounds__(256, 3)
final_kernel(float* __restrict__ outp) {
    extern __shared__ __align__(16) uint4 ws[];
    const int tid  = threadIdx.x;
    const int lane = tid & 31;
    const int wid  = tid >> 5;
    const int wm   = wid & 3;
    const int wn   = wid >> 2;
    const int mb   = blockIdx.y;
    const int nb   = blockIdx.x;
    const int par  = g_zpar;

#pragma unroll
    for (int j = 0; j < 16; ++j) {
        int linear = j*256 + tid;
        int l  = linear & 31;
        int r  = linear >> 5;
        int kk = r >> 3, n8l = r & 7;
        ws[linear] = g_wf[kk*1024 + (nb*8 + n8l)*32 + l];
    }
    __syncthreads();

    const uint4* __restrict__ yf = g_yf[par];

    float acc[2][4][4];
#pragma unroll
    for (int mi = 0; mi < 2; ++mi)
#pragma unroll
        for (int ni = 0; ni < 4; ++ni)
#pragma unroll
            for (int q = 0; q < 4; ++q) acc[mi][ni][q] = 0.f;

    const int mt0 = mb*8 + wm*2;

#pragma unroll
    for (int kk = 0; kk < 16; ++kk) {
        uint32_t ah[2][4], al[2][4];
#pragma unroll
        for (int mi = 0; mi < 2; ++mi) {
            int base = (((mt0 + mi)*16 + kk)*2)*32 + lane;
            uint4 u0 = yf[base];
            uint4 u1 = yf[base + 32];
            ah[mi][0] = u0.x; ah[mi][1] = u0.y; ah[mi][2] = u1.x; ah[mi][3] = u1.y;
            al[mi][0] = u0.z; al[mi][1] = u0.w; al[mi][2] = u1.z; al[mi][3] = u1.w;
        }
#pragma unroll
        for (int ni = 0; ni < 4; ++ni) {
            uint4 u = ws[(kk*8 + wn*4 + ni)*32 + lane];
            uint32_t bh[2] = {u.x, u.y};
            uint32_t bl[2] = {u.z, u.w};
#pragma unroll
            for (int mi = 0; mi < 2; ++mi) {
                float* c = acc[mi][ni];
                mma_bf16(c, ah[mi], bh);
                mma_bf16(c, al[mi], bh);
                mma_bf16(c, ah[mi], bl);
            }
        }
    }

    const int t2 = lane & 3, g = lane >> 2;
#pragma unroll
    for (int mi = 0; mi < 2; ++mi) {
        int row0 = mb*128 + wm*32 + mi*16 + g;
#pragma unroll
        for (int ni = 0; ni < 4; ++ni) {
            int k8  = nb*8 + wn*4 + ni;
            int col = k8*8 + t2*2;
            int gi0 = row0*DIM + col, gi1 = gi0 + 8*DIM;
            float2 b0 = *(const float2*)(g_b + gi0);
            float2 b1 = *(const float2*)(g_b + gi1);
            *(float2*)(outp + gi0) = make_float2(
                fmaxf(acc[mi][ni][0] + b0.x, 0.f),
                fmaxf(acc[mi][ni][1] + b0.y, 0.f));
            *(float2*)(outp + gi1) = make_float2(
                fmaxf(acc[mi][ni][2] + b1.x, 0.f),
                fmaxf(acc[mi][ni][3] + b1.y, 0.f));
        }
    }
}

// ---------------- launch ----------------
extern "C" void kernel_launch(void* const* d_in, const int* in_sizes, int n_in,
                              void* d_out, int out_size) {
    const float* x  = (const float*)d_in[0];
    const float* U  = (const float*)d_in[1];
    const float* ub = (const float*)d_in[2];
    const float* A  = (const float*)d_in[3];
    const float* B  = (const float*)d_in[4];
    (void)in_sizes; (void)n_in; (void)out_size;

    static int attr_done = 0;
    if (!attr_done) {
        cudaFuncSetAttribute(iter_kernel,
                             cudaFuncAttributeMaxDynamicSharedMemorySize, WS_BYTES);
        cudaFuncSetAttribute(final_kernel,
                             cudaFuncAttributeMaxDynamicSharedMemorySize, WS_BYTES);
        attr_done = 1;
    }

    prep_kernel<<<DIM, DIM>>>(U, A, B);
    dim3 p2grid(16, 32);
    prep2_kernel<<<p2grid, 32>>>();
    init_kernel<<<YF_ELEMS/256, 256>>>();

    dim3 bgrid(2, 256);
    bias_gemm<<<bgrid, 256>>>(x, ub);

    dim3 igrid(4, 256);
    float t = 1.0f;
    for (int i = 1; i <= MAX_IT; ++i) {
        float tn   = 0.5f * (1.0f + sqrtf(1.0f + 4.0f * t * t));
        float beta = (t - 1.0f) / tn;
        iter_kernel<<<igrid, 256, WS_BYTES>>>(beta, (i - 1) & 1, i - 1);
        t = tn;
    }
    final_kernel<<<igrid, 256, WS_BYTES>>>((float*)d_out);
}

// round 13
// speedup vs baseline: 1.0527x; 1.0527x over previous
#include <cuda_runtime.h>
#include <cuda_bf16.h>
#include <math.h>
#include <stdint.h>

#define BATCH    32768
#define DIM      256
#define MAX_IT   40
#define NCTAS    1024              // grid (4, 256)
#define YF_ELEMS (2048*16*2*32)    // [mtile][kk16][half][lane] uint4
#define XS_ELEMS (BATCH*128)       // [row*128 + col/2] uint2
#define WS_BYTES 65536             // 4096 uint4: [kk][n8l][lane]

// ---------------- device scratch ----------------
__device__ uint4 g_yf[2][YF_ELEMS];     // y as A-fragments (hi,hi,lo,lo), ping-pong
__device__ uint2 g_xs[2][XS_ELEMS];     // x as interleaved bf16 splits, ping-pong
__device__ uint4 g_wf[16*32*32];        // W as B-fragments [kk][n8][lane]
__device__ float g_b[BATCH*DIM];
__device__ float g_WU[DIM*DIM];         // U^T for bias GEMM
__device__ __nv_bfloat16 g_w0[DIM*DIM]; // Weff hi split [k][n] (prep staging)
__device__ __nv_bfloat16 g_w1[DIM*DIM]; // Weff lo split
__device__ float g_partial[NCTAS*2];
__device__ int   g_ctr[MAX_IT+2];
__device__ int   g_active;
__device__ int   g_zpar;                // buffer index of final z (= y at exit)

// ---------------- helpers ----------------
__device__ __forceinline__ uint32_t bpack(__nv_bfloat16 a, __nv_bfloat16 b) {
    uint16_t ua = *(uint16_t*)&a, ub = *(uint16_t*)&b;
    return (uint32_t)ua | ((uint32_t)ub << 16);
}
__device__ __forceinline__ float2 bunpack(uint32_t u) {
    __nv_bfloat162 h = *(__nv_bfloat162*)&u;
    return make_float2(__bfloat162float(h.x), __bfloat162float(h.y));
}
__device__ __forceinline__ uint32_t split_hi(float a, float b,
                                             float& ra, float& rb) {
    __nv_bfloat16 ha = __float2bfloat16(a), hb = __float2bfloat16(b);
    ra = a - __bfloat162float(ha);
    rb = b - __bfloat162float(hb);
    return bpack(ha, hb);
}
__device__ __forceinline__ uint32_t pack_lo(float ra, float rb) {
    return bpack(__float2bfloat16(ra), __float2bfloat16(rb));
}
__device__ __forceinline__ void mma_bf16(float* c, const uint32_t* a, const uint32_t* b) {
    asm volatile(
        "mma.sync.aligned.m16n8k16.row.col.f32.bf16.bf16.f32 "
        "{%0,%1,%2,%3}, {%4,%5,%6,%7}, {%8,%9}, {%0,%1,%2,%3};"
        : "+f"(c[0]), "+f"(c[1]), "+f"(c[2]), "+f"(c[3])
        : "r"(a[0]), "r"(a[1]), "r"(a[2]), "r"(a[3]), "r"(b[0]), "r"(b[1]));
}

// fp32x2 helpers for the bias GEMM
__device__ __forceinline__ unsigned long long pack2(float v) {
    unsigned long long r; unsigned u = __float_as_uint(v);
    asm("mov.b64 %0, {%1, %1};" : "=l"(r) : "r"(u));
    return r;
}
__device__ __forceinline__ void ffma2(unsigned long long& d,
                                      unsigned long long a, unsigned long long b) {
    asm("fma.rn.f32x2 %0, %1, %2, %0;" : "+l"(d) : "l"(a), "l"(b));
}
__device__ __forceinline__ float lo32(unsigned long long v) {
    return __uint_as_float((unsigned)(v & 0xffffffffull));
}
__device__ __forceinline__ float hi32(unsigned long long v) {
    return __uint_as_float((unsigned)(v >> 32));
}

// ---------------- prep: U^T, Weff -> bf16 splits (row-major staging) ----------
__global__ void prep_kernel(const float* __restrict__ U,
                            const float* __restrict__ A,
                            const float* __restrict__ B) {
    int i = blockIdx.x;    // k
    int j = threadIdx.x;   // n
    g_WU[i*DIM + j] = U[j*DIM + i];
    float s = 0.f;
#pragma unroll 8
    for (int p = 0; p < DIM; ++p)
        s = fmaf(A[p*DIM + i], A[p*DIM + j], s);
    float w = -s + B[j*DIM + i] - B[i*DIM + j];
    if (i == j) w += 0.8f;                    // (1-m), m=0.2
    __nv_bfloat16 h0 = __float2bfloat16(w);
    __nv_bfloat16 h1 = __float2bfloat16(w - __bfloat162float(h0));
    g_w0[i*DIM + j] = h0;
    g_w1[i*DIM + j] = h1;
}

// ---------------- prep2: pack W into B-fragment order ----------------
// B frag m16n8k16 (col): lane T: b0={B[k0][n],B[k0+1][n]}, b1={B[k0+8][n],B[k0+9][n]}
// with k0 = kk*16 + 2*(T%4), n = n8*8 + T/4.
__global__ void prep2_kernel() {
    int kk = blockIdx.x, n8 = blockIdx.y, lane = threadIdx.x;
    int k0 = kk*16 + 2*(lane & 3);
    int n  = n8*8 + (lane >> 2);
    uint4 u;
    u.x = bpack(g_w0[(k0    )*DIM + n], g_w0[(k0+1)*DIM + n]);
    u.y = bpack(g_w0[(k0 + 8)*DIM + n], g_w0[(k0+9)*DIM + n]);
    u.z = bpack(g_w1[(k0    )*DIM + n], g_w1[(k0+1)*DIM + n]);
    u.w = bpack(g_w1[(k0 + 8)*DIM + n], g_w1[(k0+9)*DIM + n]);
    g_wf[(kk*32 + n8)*32 + lane] = u;
}

// ---------------- flags: counters and gate state ----------------
__global__ void flags_kernel() {
    int i = threadIdx.x;
    if (i == 0) { g_active = 1; g_zpar = 0; }
    if (i <= MAX_IT + 1) g_ctr[i] = 0;
}

// ---------------- bias GEMM (runs once, exact fp32): b = x @ U^T + ub ----------
__launch_bounds__(256, 2)
__global__ void bias_gemm(const float* __restrict__ Ap, const float* __restrict__ ub) {
    __shared__ float As[16][132];
    __shared__ float Bs[16][128];
    const int tid = threadIdx.x;
    const int tx  = tid & 15, ty = tid >> 4;
    const int m0  = blockIdx.y * 128, n0 = blockIdx.x * 128;
    const int ra = tid >> 2, ca = (tid & 3) << 2;
    const int rb = tid >> 5, cb = (tid & 31) << 2;
    unsigned long long acc[8][4];
#pragma unroll
    for (int i = 0; i < 8; ++i)
#pragma unroll
        for (int j = 0; j < 4; ++j) acc[i][j] = 0ull;
    for (int k0 = 0; k0 < DIM; k0 += 16) {
        float4 a0 = *(const float4*)(Ap + (m0 + ra     ) * DIM + k0 + ca);
        float4 a1 = *(const float4*)(Ap + (m0 + ra + 64) * DIM + k0 + ca);
        float4 b0 = *(const float4*)(g_WU + (k0 + rb    ) * DIM + n0 + cb);
        float4 b1 = *(const float4*)(g_WU + (k0 + rb + 8) * DIM + n0 + cb);
        __syncthreads();
        As[ca+0][ra] = a0.x;  As[ca+1][ra] = a0.y;
        As[ca+2][ra] = a0.z;  As[ca+3][ra] = a0.w;
        As[ca+0][ra+64] = a1.x;  As[ca+1][ra+64] = a1.y;
        As[ca+2][ra+64] = a1.z;  As[ca+3][ra+64] = a1.w;
        *(float4*)&Bs[rb  ][cb] = b0;
        *(float4*)&Bs[rb+8][cb] = b1;
        __syncthreads();
#pragma unroll
        for (int kk = 0; kk < 16; ++kk) {
            unsigned long long pb[4], pa[8];
#pragma unroll
            for (int j = 0; j < 4; ++j)
                pb[j] = *(const unsigned long long*)&Bs[kk][tx*2 + j*32];
#pragma unroll
            for (int i = 0; i < 8; ++i) pa[i] = pack2(As[kk][ty*8 + i]);
#pragma unroll
            for (int i = 0; i < 8; ++i)
#pragma unroll
                for (int j = 0; j < 4; ++j) ffma2(acc[i][j], pa[i], pb[j]);
        }
    }
    float2 u[4];
#pragma unroll
    for (int j = 0; j < 4; ++j) u[j] = *(const float2*)(ub + n0 + tx*2 + j*32);
#pragma unroll
    for (int i = 0; i < 8; ++i) {
        float* base = g_b + (m0 + ty*8 + i)*DIM + n0;
#pragma unroll
        for (int j = 0; j < 4; ++j) {
            float2 g;
            g.x = lo32(acc[i][j]) + u[j].x;
            g.y = hi32(acc[i][j]) + u[j].y;
            *(float2*)(base + tx*2 + j*32) = g;
        }
    }
}

// ---------------- start: body 1 analytically (y0=x0=0, beta1=0) --------------
// x1 = y1 = relu(b/2); write y1 frags to g_yf[1], x1 splits to g_xs[1].
__global__ void start_kernel() {
    int idx  = blockIdx.x * blockDim.x + threadIdx.x;   // 0..2M-1
    int lane = idx & 31;
    int k8   = (idx >> 5) & 31;
    int mt   = idx >> 10;
    int row0 = mt*16 + (lane >> 2);
    int col  = k8*8 + (lane & 3)*2;
    int gi0  = row0*DIM + col, gi1 = gi0 + 8*DIM;
    float2 b0 = *(const float2*)(g_b + gi0);
    float2 b1 = *(const float2*)(g_b + gi1);
    float v00 = fmaxf(0.5f*b0.x, 0.f), v01 = fmaxf(0.5f*b0.y, 0.f);
    float v10 = fmaxf(0.5f*b1.x, 0.f), v11 = fmaxf(0.5f*b1.y, 0.f);
    float r0, r1, r2, r3;
    uint32_t h0 = split_hi(v00, v01, r0, r1);
    uint32_t l0 = pack_lo(r0, r1);
    uint32_t h1 = split_hi(v10, v11, r2, r3);
    uint32_t l1 = pack_lo(r2, r3);
    int yidx = ((mt*16 + (k8 >> 1))*2 + (k8 & 1))*32 + lane;
    g_yf[1][yidx] = make_uint4(h0, h1, l0, l1);
    g_xs[1][gi0 >> 1] = make_uint2(h0, l0);
    g_xs[1][gi1 >> 1] = make_uint2(h1, l1);
}

// ---------------- iteration kernel (bodies 2..40) ----------
// CTA tile 128M x 64N; 8 warps (4 M x 2 N), warp tile 32x32.
// G = a0@w0 + a1@w0 + a0@w1; epilogue: err partials (fn in regs only),
// x' = relu(0.5*(y+G+b)); y' = x' + beta*(x'-x); merged last-CTA check.
__global__ void __launch_bounds__(256, 3)
iter_kernel(float beta, int par, int it) {
    if (g_active == 0) return;
    extern __shared__ __align__(16) uint4 ws[];   // [kk][n8l][lane] = 4096 uint4
    const int tid  = threadIdx.x;
    const int lane = tid & 31;
    const int wid  = tid >> 5;
    const int wm   = wid & 3;          // M slice (32 rows)
    const int wn   = wid >> 2;         // N slice (32 cols)
    const int mb   = blockIdx.y;       // 0..255
    const int nb   = blockIdx.x;       // 0..3

    // ---- stage this CTA's W-fragment slice (64 cols) into smem ----
#pragma unroll
    for (int j = 0; j < 16; ++j) {
        int linear = j*256 + tid;              // (kk*8 + n8l)*32 + lane
        int l  = linear & 31;
        int r  = linear >> 5;                  // 0..127
        int kk = r >> 3, n8l = r & 7;
        ws[linear] = g_wf[kk*1024 + (nb*8 + n8l)*32 + l];
    }
    __syncthreads();

    const uint4* __restrict__ yf = g_yf[par];

    float acc[2][4][4];
#pragma unroll
    for (int mi = 0; mi < 2; ++mi)
#pragma unroll
        for (int ni = 0; ni < 4; ++ni)
#pragma unroll
            for (int q = 0; q < 4; ++q) acc[mi][ni][q] = 0.f;

    const int mt0 = mb*8 + wm*2;

#pragma unroll
    for (int kk = 0; kk < 16; ++kk) {
        uint32_t ah[2][4], al[2][4];
#pragma unroll
        for (int mi = 0; mi < 2; ++mi) {
            int base = (((mt0 + mi)*16 + kk)*2)*32 + lane;
            uint4 u0 = yf[base];
            uint4 u1 = yf[base + 32];
            ah[mi][0] = u0.x; ah[mi][1] = u0.y; ah[mi][2] = u1.x; ah[mi][3] = u1.y;
            al[mi][0] = u0.z; al[mi][1] = u0.w; al[mi][2] = u1.z; al[mi][3] = u1.w;
        }
#pragma unroll
        for (int ni = 0; ni < 4; ++ni) {
            uint4 u = ws[(kk*8 + wn*4 + ni)*32 + lane];
            uint32_t bh[2] = {u.x, u.y};
            uint32_t bl[2] = {u.z, u.w};
#pragma unroll
            for (int mi = 0; mi < 2; ++mi) {
                float* c = acc[mi][ni];
                mma_bf16(c, ah[mi], bh);
                mma_bf16(c, al[mi], bh);
                mma_bf16(c, ah[mi], bl);
            }
        }
    }

    // ---- fused epilogue ----
    const uint2* __restrict__ xs = g_xs[par];
    uint2* __restrict__ xsw = g_xs[par ^ 1];
    uint4* __restrict__ yfw = g_yf[par ^ 1];
    const int t2 = lane & 3, g = lane >> 2;
    float sn = 0.f, sd = 0.f;

#pragma unroll
    for (int mi = 0; mi < 2; ++mi) {
        int row0 = mb*128 + wm*32 + mi*16 + g;
#pragma unroll
        for (int ni = 0; ni < 4; ++ni) {
            int k8  = nb*8 + wn*4 + ni;
            int col = k8*8 + t2*2;
            int yidx = (((mt0 + mi)*16 + (k8 >> 1))*2 + (k8 & 1))*32 + lane;
            uint4 yu = yf[yidx];
            float2 a0h = bunpack(yu.x), a1h = bunpack(yu.y);
            float2 a0l = bunpack(yu.z), a1l = bunpack(yu.w);
            float y00 = a0h.x + a0l.x, y01 = a0h.y + a0l.y;
            float y10 = a1h.x + a1l.x, y11 = a1h.y + a1l.y;
            float g00 = acc[mi][ni][0], g01 = acc[mi][ni][1];
            float g10 = acc[mi][ni][2], g11 = acc[mi][ni][3];
            int gi0 = row0*DIM + col, gi1 = gi0 + 8*DIM;
            float2 b0 = *(const float2*)(g_b + gi0);
            float2 b1 = *(const float2*)(g_b + gi1);
            float fn00 = fmaxf(g00 + b0.x, 0.f), fn01 = fmaxf(g01 + b0.y, 0.f);
            float fn10 = fmaxf(g10 + b1.x, 0.f), fn11 = fmaxf(g11 + b1.y, 0.f);
            float d0 = y00-fn00, d1 = y01-fn01, d2 = y10-fn10, d3 = y11-fn11;
            sn = fmaf(d0,d0,sn); sn = fmaf(d1,d1,sn);
            sn = fmaf(d2,d2,sn); sn = fmaf(d3,d3,sn);
            sd = fmaf(y00,y00,sd); sd = fmaf(y01,y01,sd);
            sd = fmaf(y10,y10,sd); sd = fmaf(y11,y11,sd);
            float xn00 = fmaxf(0.5f*(y00 + g00 + b0.x), 0.f);
            float xn01 = fmaxf(0.5f*(y01 + g01 + b0.y), 0.f);
            float xn10 = fmaxf(0.5f*(y10 + g10 + b1.x), 0.f);
            float xn11 = fmaxf(0.5f*(y11 + g11 + b1.y), 0.f);
            int xi0 = gi0 >> 1, xi1 = gi1 >> 1;
            uint2 xu0 = xs[xi0], xu1 = xs[xi1];
            float2 x0h = bunpack(xu0.x), x0l = bunpack(xu0.y);
            float2 x1h = bunpack(xu1.x), x1l = bunpack(xu1.y);
            float yn00 = xn00 + beta*(xn00 - (x0h.x + x0l.x));
            float yn01 = xn01 + beta*(xn01 - (x0h.y + x0l.y));
            float yn10 = xn10 + beta*(xn10 - (x1h.x + x1l.x));
            float yn11 = xn11 + beta*(xn11 - (x1h.y + x1l.y));
            float r0, r1, r2, r3;
            uint32_t xh0 = split_hi(xn00, xn01, r0, r1);
            xsw[xi0] = make_uint2(xh0, pack_lo(r0, r1));
            uint32_t xh1 = split_hi(xn10, xn11, r2, r3);
            xsw[xi1] = make_uint2(xh1, pack_lo(r2, r3));
            uint32_t yh0 = split_hi(yn00, yn01, r0, r1);
            uint32_t yh1 = split_hi(yn10, yn11, r2, r3);
            yfw[yidx] = make_uint4(yh0, yh1, pack_lo(r0, r1), pack_lo(r2, r3));
        }
    }

    // ---- deterministic block reduction (reuse smem after sync) ----
    __syncthreads();
    float* red = (float*)ws;
    red[tid] = sn;  red[256 + tid] = sd;
    __syncthreads();
#pragma unroll
    for (int s = 128; s > 0; s >>= 1) {
        if (tid < s) { red[tid] += red[tid + s]; red[256 + tid] += red[256 + tid + s]; }
        __syncthreads();
    }
    const int cta = mb*4 + nb;
    if (tid == 0) {
        g_partial[cta*2    ] = red[0];
        g_partial[cta*2 + 1] = red[256];
    }

    // ---- merged convergence check: last CTA reduces and gates ----
    __shared__ int islast;
    __threadfence();
    if (tid == 0) islast = (atomicAdd(&g_ctr[it], 1) == NCTAS - 1);
    __syncthreads();
    if (islast) {
        float a = 0.f, b = 0.f;
#pragma unroll
        for (int k = 0; k < 4; ++k) {
            a += g_partial[2*(tid + k*256)    ];
            b += g_partial[2*(tid + k*256) + 1];
        }
        red[tid] = a; red[256 + tid] = b;
        __syncthreads();
#pragma unroll
        for (int s = 128; s > 0; s >>= 1) {
            if (tid < s) { red[tid] += red[tid + s]; red[256 + tid] += red[256 + tid + s]; }
            __syncthreads();
        }
        if (tid == 0) {
            float err = sqrtf(red[0]) / (1e-6f + sqrtf(red[256]));
            if (!(err > 1e-4f)) {
                g_active = 0;
                g_zpar = par;      // z = y of body (it) lives in buffer `par`
            }
        }
    }
}

// ---------------- final kernel: out = relu(z @ W + b), z = g_yf[g_zpar] ------
__global__ void __launch_bounds__(256, 3)
final_kernel(float* __restrict__ outp) {
    extern __shared__ __align__(16) uint4 ws[];
    const int tid  = threadIdx.x;
    const int lane = tid & 31;
    const int wid  = tid >> 5;
    const int wm   = wid & 3;
    const int wn   = wid >> 2;
    const int mb   = blockIdx.y;
    const int nb   = blockIdx.x;
    const int par  = g_zpar;

#pragma unroll
    for (int j = 0; j < 16; ++j) {
        int linear = j*256 + tid;
        int l  = linear & 31;
        int r  = linear >> 5;
        int kk = r >> 3, n8l = r & 7;
        ws[linear] = g_wf[kk*1024 + (nb*8 + n8l)*32 + l];
    }
    __syncthreads();

    const uint4* __restrict__ yf = g_yf[par];

    float acc[2][4][4];
#pragma unroll
    for (int mi = 0; mi < 2; ++mi)
#pragma unroll
        for (int ni = 0; ni < 4; ++ni)
#pragma unroll
            for (int q = 0; q < 4; ++q) acc[mi][ni][q] = 0.f;

    const int mt0 = mb*8 + wm*2;

#pragma unroll
    for (int kk = 0; kk < 16; ++kk) {
        uint32_t ah[2][4], al[2][4];
#pragma unroll
        for (int mi = 0; mi < 2; ++mi) {
            int base = (((mt0 + mi)*16 + kk)*2)*32 + lane;
            uint4 u0 = yf[base];
            uint4 u1 = yf[base + 32];
            ah[mi][0] = u0.x; ah[mi][1] = u0.y; ah[mi][2] = u1.x; ah[mi][3] = u1.y;
            al[mi][0] = u0.z; al[mi][1] = u0.w; al[mi][2] = u1.z; al[mi][3] = u1.w;
        }
#pragma unroll
        for (int ni = 0; ni < 4; ++ni) {
            uint4 u = ws[(kk*8 + wn*4 + ni)*32 + lane];
            uint32_t bh[2] = {u.x, u.y};
            uint32_t bl[2] = {u.z, u.w};
#pragma unroll
            for (int mi = 0; mi < 2; ++mi) {
                float* c = acc[mi][ni];
                mma_bf16(c, ah[mi], bh);
                mma_bf16(c, al[mi], bh);
                mma_bf16(c, ah[mi], bl);
            }
        }
    }

    const int t2 = lane & 3, g = lane >> 2;
#pragma unroll
    for (int mi = 0; mi < 2; ++mi) {
        int row0 = mb*128 + wm*32 + mi*16 + g;
#pragma unroll
        for (int ni = 0; ni < 4; ++ni) {
            int k8  = nb*8 + wn*4 + ni;
            int col = k8*8 + t2*2;
            int gi0 = row0*DIM + col, gi1 = gi0 + 8*DIM;
            float2 b0 = *(const float2*)(g_b + gi0);
            float2 b1 = *(const float2*)(g_b + gi1);
            *(float2*)(outp + gi0) = make_float2(
                fmaxf(acc[mi][ni][0] + b0.x, 0.f),
                fmaxf(acc[mi][ni][1] + b0.y, 0.f));
            *(float2*)(outp + gi1) = make_float2(
                fmaxf(acc[mi][ni][2] + b1.x, 0.f),
                fmaxf(acc[mi][ni][3] + b1.y, 0.f));
        }
    }
}

// ---------------- launch ----------------
extern "C" void kernel_launch(void* const* d_in, const int* in_sizes, int n_in,
                              void* d_out, int out_size) {
    const float* x  = (const float*)d_in[0];
    const float* U  = (const float*)d_in[1];
    const float* ub = (const float*)d_in[2];
    const float* A  = (const float*)d_in[3];
    const float* B  = (const float*)d_in[4];
    (void)in_sizes; (void)n_in; (void)out_size;

    static int attr_done = 0;
    if (!attr_done) {
        cudaFuncSetAttribute(iter_kernel,
                             cudaFuncAttributeMaxDynamicSharedMemorySize, WS_BYTES);
        cudaFuncSetAttribute(final_kernel,
                             cudaFuncAttributeMaxDynamicSharedMemorySize, WS_BYTES);
        attr_done = 1;
    }

    prep_kernel<<<DIM, DIM>>>(U, A, B);
    dim3 p2grid(16, 32);
    prep2_kernel<<<p2grid, 32>>>();
    flags_kernel<<<1, 64>>>();

    dim3 bgrid(2, 256);
    bias_gemm<<<bgrid, 256>>>(x, ub);

    start_kernel<<<YF_ELEMS/256, 256>>>();       // body 1: y1 = x1 = relu(b/2)

    // bodies 2..40: kernel i computes forward i + err_{i-1}; gate exact as R11
    dim3 igrid(4, 256);
    float t = 1.6180339887f;                     // t1 (after body 1)
    for (int i = 2; i <= MAX_IT; ++i) {
        float tn   = 0.5f * (1.0f + sqrtf(1.0f + 4.0f * t * t));
        float beta = (t - 1.0f) / tn;
        iter_kernel<<<igrid, 256, WS_BYTES>>>(beta, (i - 1) & 1, i - 1);
        t = tn;
    }
    final_kernel<<<igrid, 256, WS_BYTES>>>((float*)d_out);
}

// round 14
// speedup vs baseline: 1.0706x; 1.0170x over previous
#include <cuda_runtime.h>
#include <cuda_bf16.h>
#include <math.h>
#include <stdint.h>

#define BATCH    32768
#define DIM      256
#define MAX_IT   40
#define NCTAS    1024              // grid (4, 256)
#define YF_ELEMS (2048*16*2*32)    // [mtile][kk16][half][lane] uint4
#define XS_ELEMS (BATCH*128)       // [row*128 + col/2] uint2
#define WS_BYTES 65536             // 4096 uint4: [kk][n8l][lane]

// ---------------- device scratch ----------------
__device__ uint4 g_yf[2][YF_ELEMS];     // y as A-fragments (hi,hi,lo,lo), ping-pong
__device__ uint2 g_xs[2][XS_ELEMS];     // x as interleaved bf16 splits, ping-pong
__device__ uint2 g_bs[XS_ELEMS];        // b as interleaved bf16 splits
__device__ uint4 g_wf[16*32*32];        // W as B-fragments [kk][n8][lane]
__device__ uint4 g_uf[16*32*32];        // U^T as B-fragments
__device__ __nv_bfloat16 g_w0[DIM*DIM]; // Weff hi split [k][n] (prep staging)
__device__ __nv_bfloat16 g_w1[DIM*DIM]; // Weff lo split
__device__ __nv_bfloat16 g_u0[DIM*DIM]; // U^T hi split
__device__ __nv_bfloat16 g_u1[DIM*DIM]; // U^T lo split
__device__ float g_partial[NCTAS*2];
__device__ int   g_ctr[MAX_IT+2];
__device__ int   g_active;
__device__ int   g_zpar;                // buffer index of final z (= y at exit)

// ---------------- helpers ----------------
__device__ __forceinline__ uint32_t bpack(__nv_bfloat16 a, __nv_bfloat16 b) {
    uint16_t ua = *(uint16_t*)&a, ub = *(uint16_t*)&b;
    return (uint32_t)ua | ((uint32_t)ub << 16);
}
__device__ __forceinline__ float2 bunpack(uint32_t u) {
    __nv_bfloat162 h = *(__nv_bfloat162*)&u;
    return make_float2(__bfloat162float(h.x), __bfloat162float(h.y));
}
__device__ __forceinline__ float2 sunpack(uint2 u) {   // split pair -> 2 floats
    float2 h = bunpack(u.x), l = bunpack(u.y);
    return make_float2(h.x + l.x, h.y + l.y);
}
__device__ __forceinline__ uint32_t split_hi(float a, float b,
                                             float& ra, float& rb) {
    __nv_bfloat16 ha = __float2bfloat16(a), hb = __float2bfloat16(b);
    ra = a - __bfloat162float(ha);
    rb = b - __bfloat162float(hb);
    return bpack(ha, hb);
}
__device__ __forceinline__ uint32_t pack_lo(float ra, float rb) {
    return bpack(__float2bfloat16(ra), __float2bfloat16(rb));
}
__device__ __forceinline__ void mma_bf16(float* c, const uint32_t* a, const uint32_t* b) {
    asm volatile(
        "mma.sync.aligned.m16n8k16.row.col.f32.bf16.bf16.f32 "
        "{%0,%1,%2,%3}, {%4,%5,%6,%7}, {%8,%9}, {%0,%1,%2,%3};"
        : "+f"(c[0]), "+f"(c[1]), "+f"(c[2]), "+f"(c[3])
        : "r"(a[0]), "r"(a[1]), "r"(a[2]), "r"(a[3]), "r"(b[0]), "r"(b[1]));
}

// ---------------- prep: Weff and U^T -> bf16 splits ----------
__global__ void prep_kernel(const float* __restrict__ U,
                            const float* __restrict__ A,
                            const float* __restrict__ B) {
    int i = blockIdx.x;    // k
    int j = threadIdx.x;   // n
    // U^T[i][j] = U[j][i]
    float u = U[j*DIM + i];
    __nv_bfloat16 uh = __float2bfloat16(u);
    g_u0[i*DIM + j] = uh;
    g_u1[i*DIM + j] = __float2bfloat16(u - __bfloat162float(uh));
    float s = 0.f;
#pragma unroll 8
    for (int p = 0; p < DIM; ++p)
        s = fmaf(A[p*DIM + i], A[p*DIM + j], s);
    float w = -s + B[j*DIM + i] - B[i*DIM + j];
    if (i == j) w += 0.8f;                    // (1-m), m=0.2
    __nv_bfloat16 h0 = __float2bfloat16(w);
    g_w0[i*DIM + j] = h0;
    g_w1[i*DIM + j] = __float2bfloat16(w - __bfloat162float(h0));
}

// ---------------- prep2: pack W and U^T into B-fragment order ----------------
// B frag m16n8k16 (col): lane T: b0={B[k0][n],B[k0+1][n]}, b1={B[k0+8][n],B[k0+9][n]}
// with k0 = kk*16 + 2*(T%4), n = n8*8 + T/4.
__global__ void prep2_kernel() {
    int kk = blockIdx.x, n8 = blockIdx.y, lane = threadIdx.x;
    int k0 = kk*16 + 2*(lane & 3);
    int n  = n8*8 + (lane >> 2);
    int o  = (kk*32 + n8)*32 + lane;
    uint4 u;
    u.x = bpack(g_w0[(k0    )*DIM + n], g_w0[(k0+1)*DIM + n]);
    u.y = bpack(g_w0[(k0 + 8)*DIM + n], g_w0[(k0+9)*DIM + n]);
    u.z = bpack(g_w1[(k0    )*DIM + n], g_w1[(k0+1)*DIM + n]);
    u.w = bpack(g_w1[(k0 + 8)*DIM + n], g_w1[(k0+9)*DIM + n]);
    g_wf[o] = u;
    u.x = bpack(g_u0[(k0    )*DIM + n], g_u0[(k0+1)*DIM + n]);
    u.y = bpack(g_u0[(k0 + 8)*DIM + n], g_u0[(k0+9)*DIM + n]);
    u.z = bpack(g_u1[(k0    )*DIM + n], g_u1[(k0+1)*DIM + n]);
    u.w = bpack(g_u1[(k0 + 8)*DIM + n], g_u1[(k0+9)*DIM + n]);
    g_uf[o] = u;
}

// ---------------- flags ----------------
__global__ void flags_kernel() {
    int i = threadIdx.x;
    if (i == 0) { g_active = 1; g_zpar = 0; }
    if (i <= MAX_IT + 1) g_ctr[i] = 0;
}

// ---------------- packx: input x -> A-fragments in g_yf[0] (scratch) --------
__global__ void packx_kernel(const float* __restrict__ xin) {
    int idx  = blockIdx.x * blockDim.x + threadIdx.x;   // 0..2M-1
    int lane = idx & 31;
    int k8   = (idx >> 5) & 31;
    int mt   = idx >> 10;
    int row0 = mt*16 + (lane >> 2);
    int col  = k8*8 + (lane & 3)*2;
    int gi0  = row0*DIM + col, gi1 = gi0 + 8*DIM;
    float2 v0 = *(const float2*)(xin + gi0);
    float2 v1 = *(const float2*)(xin + gi1);
    float r0, r1, r2, r3;
    uint32_t h0 = split_hi(v0.x, v0.y, r0, r1);
    uint32_t h1 = split_hi(v1.x, v1.y, r2, r3);
    int yidx = ((mt*16 + (k8 >> 1))*2 + (k8 & 1))*32 + lane;
    g_yf[0][yidx] = make_uint4(h0, h1, pack_lo(r0, r1), pack_lo(r2, r3));
}

// ---------------- bias GEMM (tensor): b = x @ U^T + ub -> split storage ------
__global__ void __launch_bounds__(256, 3)
bias_tensor(const float* __restrict__ ub) {
    extern __shared__ __align__(16) uint4 ws[];
    const int tid  = threadIdx.x;
    const int lane = tid & 31;
    const int wid  = tid >> 5;
    const int wm   = wid & 3;
    const int wn   = wid >> 2;
    const int mb   = blockIdx.y;
    const int nb   = blockIdx.x;

#pragma unroll
    for (int j = 0; j < 16; ++j) {
        int linear = j*256 + tid;
        int l  = linear & 31;
        int r  = linear >> 5;
        int kk = r >> 3, n8l = r & 7;
        ws[linear] = g_uf[kk*1024 + (nb*8 + n8l)*32 + l];
    }
    __syncthreads();

    const uint4* __restrict__ yf = g_yf[0];   // x fragments

    float acc[2][4][4];
#pragma unroll
    for (int mi = 0; mi < 2; ++mi)
#pragma unroll
        for (int ni = 0; ni < 4; ++ni)
#pragma unroll
            for (int q = 0; q < 4; ++q) acc[mi][ni][q] = 0.f;

    const int mt0 = mb*8 + wm*2;

#pragma unroll
    for (int kk = 0; kk < 16; ++kk) {
        uint32_t ah[2][4], al[2][4];
#pragma unroll
        for (int mi = 0; mi < 2; ++mi) {
            int base = (((mt0 + mi)*16 + kk)*2)*32 + lane;
            uint4 u0 = yf[base];
            uint4 u1 = yf[base + 32];
            ah[mi][0] = u0.x; ah[mi][1] = u0.y; ah[mi][2] = u1.x; ah[mi][3] = u1.y;
            al[mi][0] = u0.z; al[mi][1] = u0.w; al[mi][2] = u1.z; al[mi][3] = u1.w;
        }
#pragma unroll
        for (int ni = 0; ni < 4; ++ni) {
            uint4 u = ws[(kk*8 + wn*4 + ni)*32 + lane];
            uint32_t bh[2] = {u.x, u.y};
            uint32_t bl[2] = {u.z, u.w};
#pragma unroll
            for (int mi = 0; mi < 2; ++mi) {
                float* c = acc[mi][ni];
                mma_bf16(c, ah[mi], bh);
                mma_bf16(c, al[mi], bh);
                mma_bf16(c, ah[mi], bl);
            }
        }
    }

    const int t2 = lane & 3, g = lane >> 2;
#pragma unroll
    for (int mi = 0; mi < 2; ++mi) {
        int row0 = mb*128 + wm*32 + mi*16 + g;
#pragma unroll
        for (int ni = 0; ni < 4; ++ni) {
            int k8  = nb*8 + wn*4 + ni;
            int col = k8*8 + t2*2;
            int gi0 = row0*DIM + col, gi1 = gi0 + 8*DIM;
            float2 u = *(const float2*)(ub + col);
            float b00 = acc[mi][ni][0] + u.x, b01 = acc[mi][ni][1] + u.y;
            float b10 = acc[mi][ni][2] + u.x, b11 = acc[mi][ni][3] + u.y;
            float r0, r1, r2, r3;
            uint32_t h0 = split_hi(b00, b01, r0, r1);
            g_bs[gi0 >> 1] = make_uint2(h0, pack_lo(r0, r1));
            uint32_t h1 = split_hi(b10, b11, r2, r3);
            g_bs[gi1 >> 1] = make_uint2(h1, pack_lo(r2, r3));
        }
    }
}

// ---------------- start: body 1 analytically (y0=x0=0, beta1=0) --------------
// x1 = y1 = relu(b/2); write y1 frags to g_yf[1], x1 splits to g_xs[1].
__global__ void start_kernel() {
    int idx  = blockIdx.x * blockDim.x + threadIdx.x;   // 0..2M-1
    int lane = idx & 31;
    int k8   = (idx >> 5) & 31;
    int mt   = idx >> 10;
    int row0 = mt*16 + (lane >> 2);
    int col  = k8*8 + (lane & 3)*2;
    int gi0  = row0*DIM + col, gi1 = gi0 + 8*DIM;
    float2 b0 = sunpack(g_bs[gi0 >> 1]);
    float2 b1 = sunpack(g_bs[gi1 >> 1]);
    float v00 = fmaxf(0.5f*b0.x, 0.f), v01 = fmaxf(0.5f*b0.y, 0.f);
    float v10 = fmaxf(0.5f*b1.x, 0.f), v11 = fmaxf(0.5f*b1.y, 0.f);
    float r0, r1, r2, r3;
    uint32_t h0 = split_hi(v00, v01, r0, r1);
    uint32_t l0 = pack_lo(r0, r1);
    uint32_t h1 = split_hi(v10, v11, r2, r3);
    uint32_t l1 = pack_lo(r2, r3);
    int yidx = ((mt*16 + (k8 >> 1))*2 + (k8 & 1))*32 + lane;
    g_yf[1][yidx] = make_uint4(h0, h1, l0, l1);
    g_xs[1][gi0 >> 1] = make_uint2(h0, l0);
    g_xs[1][gi1 >> 1] = make_uint2(h1, l1);
}

// ---------------- iteration kernel (bodies 2..40) ----------
__global__ void __launch_bounds__(256, 3)
iter_kernel(float beta, int par, int it) {
    if (g_active == 0) return;
    extern __shared__ __align__(16) uint4 ws[];
    const int tid  = threadIdx.x;
    const int lane = tid & 31;
    const int wid  = tid >> 5;
    const int wm   = wid & 3;
    const int wn   = wid >> 2;
    const int mb   = blockIdx.y;
    const int nb   = blockIdx.x;

#pragma unroll
    for (int j = 0; j < 16; ++j) {
        int linear = j*256 + tid;
        int l  = linear & 31;
        int r  = linear >> 5;
        int kk = r >> 3, n8l = r & 7;
        ws[linear] = g_wf[kk*1024 + (nb*8 + n8l)*32 + l];
    }
    __syncthreads();

    const uint4* __restrict__ yf = g_yf[par];

    float acc[2][4][4];
#pragma unroll
    for (int mi = 0; mi < 2; ++mi)
#pragma unroll
        for (int ni = 0; ni < 4; ++ni)
#pragma unroll
            for (int q = 0; q < 4; ++q) acc[mi][ni][q] = 0.f;

    const int mt0 = mb*8 + wm*2;

#pragma unroll
    for (int kk = 0; kk < 16; ++kk) {
        uint32_t ah[2][4], al[2][4];
#pragma unroll
        for (int mi = 0; mi < 2; ++mi) {
            int base = (((mt0 + mi)*16 + kk)*2)*32 + lane;
            uint4 u0 = yf[base];
            uint4 u1 = yf[base + 32];
            ah[mi][0] = u0.x; ah[mi][1] = u0.y; ah[mi][2] = u1.x; ah[mi][3] = u1.y;
            al[mi][0] = u0.z; al[mi][1] = u0.w; al[mi][2] = u1.z; al[mi][3] = u1.w;
        }
#pragma unroll
        for (int ni = 0; ni < 4; ++ni) {
            uint4 u = ws[(kk*8 + wn*4 + ni)*32 + lane];
            uint32_t bh[2] = {u.x, u.y};
            uint32_t bl[2] = {u.z, u.w};
#pragma unroll
            for (int mi = 0; mi < 2; ++mi) {
                float* c = acc[mi][ni];
                mma_bf16(c, ah[mi], bh);
                mma_bf16(c, al[mi], bh);
                mma_bf16(c, ah[mi], bl);
            }
        }
    }

    // ---- fused epilogue ----
    const uint2* __restrict__ xs = g_xs[par];
    uint2* __restrict__ xsw = g_xs[par ^ 1];
    uint4* __restrict__ yfw = g_yf[par ^ 1];
    const int t2 = lane & 3, g = lane >> 2;
    float sn = 0.f, sd = 0.f;

#pragma unroll
    for (int mi = 0; mi < 2; ++mi) {
        int row0 = mb*128 + wm*32 + mi*16 + g;
#pragma unroll
        for (int ni = 0; ni < 4; ++ni) {
            int k8  = nb*8 + wn*4 + ni;
            int col = k8*8 + t2*2;
            int yidx = (((mt0 + mi)*16 + (k8 >> 1))*2 + (k8 & 1))*32 + lane;
            uint4 yu = yf[yidx];
            float2 a0h = bunpack(yu.x), a1h = bunpack(yu.y);
            float2 a0l = bunpack(yu.z), a1l = bunpack(yu.w);
            float y00 = a0h.x + a0l.x, y01 = a0h.y + a0l.y;
            float y10 = a1h.x + a1l.x, y11 = a1h.y + a1l.y;
            float g00 = acc[mi][ni][0], g01 = acc[mi][ni][1];
            float g10 = acc[mi][ni][2], g11 = acc[mi][ni][3];
            int gi0 = row0*DIM + col, gi1 = gi0 + 8*DIM;
            float2 b0 = sunpack(g_bs[gi0 >> 1]);
            float2 b1 = sunpack(g_bs[gi1 >> 1]);
            float fn00 = fmaxf(g00 + b0.x, 0.f), fn01 = fmaxf(g01 + b0.y, 0.f);
            float fn10 = fmaxf(g10 + b1.x, 0.f), fn11 = fmaxf(g11 + b1.y, 0.f);
            float d0 = y00-fn00, d1 = y01-fn01, d2 = y10-fn10, d3 = y11-fn11;
            sn = fmaf(d0,d0,sn); sn = fmaf(d1,d1,sn);
            sn = fmaf(d2,d2,sn); sn = fmaf(d3,d3,sn);
            sd = fmaf(y00,y00,sd); sd = fmaf(y01,y01,sd);
            sd = fmaf(y10,y10,sd); sd = fmaf(y11,y11,sd);
            float xn00 = fmaxf(0.5f*(y00 + g00 + b0.x), 0.f);
            float xn01 = fmaxf(0.5f*(y01 + g01 + b0.y), 0.f);
            float xn10 = fmaxf(0.5f*(y10 + g10 + b1.x), 0.f);
            float xn11 = fmaxf(0.5f*(y11 + g11 + b1.y), 0.f);
            int xi0 = gi0 >> 1, xi1 = gi1 >> 1;
            float2 xv0 = sunpack(xs[xi0]);
            float2 xv1 = sunpack(xs[xi1]);
            float yn00 = xn00 + beta*(xn00 - xv0.x);
            float yn01 = xn01 + beta*(xn01 - xv0.y);
            float yn10 = xn10 + beta*(xn10 - xv1.x);
            float yn11 = xn11 + beta*(xn11 - xv1.y);
            float r0, r1, r2, r3;
            uint32_t xh0 = split_hi(xn00, xn01, r0, r1);
            xsw[xi0] = make_uint2(xh0, pack_lo(r0, r1));
            uint32_t xh1 = split_hi(xn10, xn11, r2, r3);
            xsw[xi1] = make_uint2(xh1, pack_lo(r2, r3));
            uint32_t yh0 = split_hi(yn00, yn01, r0, r1);
            uint32_t yh1 = split_hi(yn10, yn11, r2, r3);
            yfw[yidx] = make_uint4(yh0, yh1, pack_lo(r0, r1), pack_lo(r2, r3));
        }
    }

    // ---- deterministic block reduction (reuse smem after sync) ----
    __syncthreads();
    float* red = (float*)ws;
    red[tid] = sn;  red[256 + tid] = sd;
    __syncthreads();
#pragma unroll
    for (int s = 128; s > 0; s >>= 1) {
        if (tid < s) { red[tid] += red[tid + s]; red[256 + tid] += red[256 + tid + s]; }
        __syncthreads();
    }
    const int cta = mb*4 + nb;
    if (tid == 0) {
        g_partial[cta*2    ] = red[0];
        g_partial[cta*2 + 1] = red[256];
    }

    // ---- merged convergence check: last CTA reduces and gates ----
    __shared__ int islast;
    __threadfence();
    if (tid == 0) islast = (atomicAdd(&g_ctr[it], 1) == NCTAS - 1);
    __syncthreads();
    if (islast) {
        float a = 0.f, b = 0.f;
#pragma unroll
        for (int k = 0; k < 4; ++k) {
            a += g_partial[2*(tid + k*256)    ];
            b += g_partial[2*(tid + k*256) + 1];
        }
        red[tid] = a; red[256 + tid] = b;
        __syncthreads();
#pragma unroll
        for (int s = 128; s > 0; s >>= 1) {
            if (tid < s) { red[tid] += red[tid + s]; red[256 + tid] += red[256 + tid + s]; }
            __syncthreads();
        }
        if (tid == 0) {
            float err = sqrtf(red[0]) / (1e-6f + sqrtf(red[256]));
            if (!(err > 1e-4f)) {
                g_active = 0;
                g_zpar = par;      // z = y of body (it) lives in buffer `par`
            }
        }
    }
}

// ---------------- final kernel: out = relu(z @ W + b), z = g_yf[g_zpar] ------
__global__ void __launch_bounds__(256, 3)
final_kernel(float* __restrict__ outp) {
    extern __shared__ __align__(16) uint4 ws[];
    const int tid  = threadIdx.x;
    const int lane = tid & 31;
    const int wid  = tid >> 5;
    const int wm   = wid & 3;
    const int wn   = wid >> 2;
    const int mb   = blockIdx.y;
    const int nb   = blockIdx.x;
    const int par  = g_zpar;

#pragma unroll
    for (int j = 0; j < 16; ++j) {
        int linear = j*256 + tid;
        int l  = linear & 31;
        int r  = linear >> 5;
        int kk = r >> 3, n8l = r & 7;
        ws[linear] = g_wf[kk*1024 + (nb*8 + n8l)*32 + l];
    }
    __syncthreads();

    const uint4* __restrict__ yf = g_yf[par];

    float acc[2][4][4];
#pragma unroll
    for (int mi = 0; mi < 2; ++mi)
#pragma unroll
        for (int ni = 0; ni < 4; ++ni)
#pragma unroll
            for (int q = 0; q < 4; ++q) acc[mi][ni][q] = 0.f;

    const int mt0 = mb*8 + wm*2;

#pragma unroll
    for (int kk = 0; kk < 16; ++kk) {
        uint32_t ah[2][4], al[2][4];
#pragma unroll
        for (int mi = 0; mi < 2; ++mi) {
            int base = (((mt0 + mi)*16 + kk)*2)*32 + lane;
            uint4 u0 = yf[base];
            uint4 u1 = yf[base + 32];
            ah[mi][0] = u0.x; ah[mi][1] = u0.y; ah[mi][2] = u1.x; ah[mi][3] = u1.y;
            al[mi][0] = u0.z; al[mi][1] = u0.w; al[mi][2] = u1.z; al[mi][3] = u1.w;
        }
#pragma unroll
        for (int ni = 0; ni < 4; ++ni) {
            uint4 u = ws[(kk*8 + wn*4 + ni)*32 + lane];
            uint32_t bh[2] = {u.x, u.y};
            uint32_t bl[2] = {u.z, u.w};
#pragma unroll
            for (int mi = 0; mi < 2; ++mi) {
                float* c = acc[mi][ni];
                mma_bf16(c, ah[mi], bh);
                mma_bf16(c, al[mi], bh);
                mma_bf16(c, ah[mi], bl);
            }
        }
    }

    const int t2 = lane & 3, g = lane >> 2;
#pragma unroll
    for (int mi = 0; mi < 2; ++mi) {
        int row0 = mb*128 + wm*32 + mi*16 + g;
#pragma unroll
        for (int ni = 0; ni < 4; ++ni) {
            int k8  = nb*8 + wn*4 + ni;
            int col = k8*8 + t2*2;
            int gi0 = row0*DIM + col, gi1 = gi0 + 8*DIM;
            float2 b0 = sunpack(g_bs[gi0 >> 1]);
            float2 b1 = sunpack(g_bs[gi1 >> 1]);
            *(float2*)(outp + gi0) = make_float2(
                fmaxf(acc[mi][ni][0] + b0.x, 0.f),
                fmaxf(acc[mi][ni][1] + b0.y, 0.f));
            *(float2*)(outp + gi1) = make_float2(
                fmaxf(acc[mi][ni][2] + b1.x, 0.f),
                fmaxf(acc[mi][ni][3] + b1.y, 0.f));
        }
    }
}

// ---------------- launch ----------------
extern "C" void kernel_launch(void* const* d_in, const int* in_sizes, int n_in,
                              void* d_out, int out_size) {
    const float* x  = (const float*)d_in[0];
    const float* U  = (const float*)d_in[1];
    const float* ub = (const float*)d_in[2];
    const float* A  = (const float*)d_in[3];
    const float* B  = (const float*)d_in[4];
    (void)in_sizes; (void)n_in; (void)out_size;

    static int attr_done = 0;
    if (!attr_done) {
        cudaFuncSetAttribute(bias_tensor,
                             cudaFuncAttributeMaxDynamicSharedMemorySize, WS_BYTES);
        cudaFuncSetAttribute(iter_kernel,
                             cudaFuncAttributeMaxDynamicSharedMemorySize, WS_BYTES);
        cudaFuncSetAttribute(final_kernel,
                             cudaFuncAttributeMaxDynamicSharedMemorySize, WS_BYTES);
        attr_done = 1;
    }

    prep_kernel<<<DIM, DIM>>>(U, A, B);
    dim3 p2grid(16, 32);
    prep2_kernel<<<p2grid, 32>>>();
    flags_kernel<<<1, 64>>>();

    packx_kernel<<<YF_ELEMS/256, 256>>>(x);     // x -> A-frags in g_yf[0]
    dim3 igrid(4, 256);
    bias_tensor<<<igrid, 256, WS_BYTES>>>(ub);  // b = x@U^T + ub (split store)
    start_kernel<<<YF_ELEMS/256, 256>>>();      // body 1: y1 = x1 = relu(b/2)

    // bodies 2..40: kernel i computes forward i + err_{i-1}
    float t = 1.6180339887f;                    // t1 (after body 1)
    for (int i = 2; i <= MAX_IT; ++i) {
        float tn   = 0.5f * (1.0f + sqrtf(1.0f + 4.0f * t * t));
        float beta = (t - 1.0f) / tn;
        iter_kernel<<<igrid, 256, WS_BYTES>>>(beta, (i - 1) & 1, i - 1);
        t = tn;
    }
    final_kernel<<<igrid, 256, WS_BYTES>>>((float*)d_out);
}